// round 1
// baseline (speedup 1.0000x reference)
#include <cuda_runtime.h>
#include <math.h>
#include <stdint.h>

#define CC 256
#define NN 16384
#define BB 4
#define BCN (CC*NN)

// ---------------- scratch (device globals; no allocations allowed) ----------
__device__ float g_xn[BB*BCN];
__device__ float g_t [BB*BCN];   // temp (q1/k1 pre-act, later out_pre)
__device__ float g_q [BB*BCN];
__device__ float g_k [BB*BCN];
__device__ float g_v [BB*BCN];
__device__ float g_g [BB*BCN];
__device__ float g_kvp[BB*16*CC*CC];
__device__ float g_kvT[BB*CC*CC];
__device__ float g_ks [BB*CC];
__device__ float g_z  [BB*NN];

// ---------------- helpers ----------------------------------------------------
__device__ __forceinline__ unsigned f2tf(float f){
    unsigned r; asm("cvt.rna.tf32.f32 %0, %1;" : "=r"(r) : "f"(f)); return r;
}
__device__ __forceinline__ void cpa16(float* s, const float* g){
    unsigned a = (unsigned)__cvta_generic_to_shared(s);
    asm volatile("cp.async.cg.shared.global [%0], [%1], 16;\n" :: "r"(a), "l"(g));
}
__device__ __forceinline__ void cpacommit(){ asm volatile("cp.async.commit_group;\n"); }
__device__ __forceinline__ void cpawait(){ asm volatile("cp.async.wait_group 0;\n"); }
__device__ __forceinline__ void mma8(float* d, const unsigned* a, unsigned b0, unsigned b1){
    asm volatile(
      "mma.sync.aligned.m16n8k8.row.col.f32.tf32.tf32.f32 "
      "{%0,%1,%2,%3},{%4,%5,%6,%7},{%8,%9},{%0,%1,%2,%3};\n"
      : "+f"(d[0]), "+f"(d[1]), "+f"(d[2]), "+f"(d[3])
      : "r"(a[0]), "r"(a[1]), "r"(a[2]), "r"(a[3]), "r"(b0), "r"(b1));
}
__device__ __forceinline__ float geluf(float x){
    return 0.5f * x * (1.0f + erff(x * 0.70710678118654752440f));
}
__device__ __forceinline__ float softplusf(float x){
    return fmaxf(x, 0.0f) + log1pf(expf(-fabsf(x)));
}

// ---------------- instance norm ----------------------------------------------
__global__ __launch_bounds__(256) void instnorm_kernel(
    const float* __restrict__ x, float* __restrict__ y)
{
    const long base = (long)blockIdx.x * NN;
    const float4* xp = (const float4*)(x + base);
    float4* yp = (float4*)(y + base);
    const int tid = threadIdx.x;
    float4 v[16];
    float s = 0.f, s2 = 0.f;
    #pragma unroll
    for (int i = 0; i < 16; ++i){
        v[i] = xp[tid + i*256];
        s  += v[i].x + v[i].y + v[i].z + v[i].w;
        s2 += v[i].x*v[i].x + v[i].y*v[i].y + v[i].z*v[i].z + v[i].w*v[i].w;
    }
    #pragma unroll
    for (int o = 16; o; o >>= 1){
        s  += __shfl_xor_sync(0xffffffffu, s,  o);
        s2 += __shfl_xor_sync(0xffffffffu, s2, o);
    }
    __shared__ float sh[16];
    const int w = tid >> 5, lane = tid & 31;
    if (lane == 0){ sh[w] = s; sh[8+w] = s2; }
    __syncthreads();
    if (tid == 0){
        float ts = 0.f, ts2 = 0.f;
        #pragma unroll
        for (int i = 0; i < 8; ++i){ ts += sh[i]; ts2 += sh[8+i]; }
        float mu  = ts * (1.0f/NN);
        float var = ts2 * (1.0f/NN) - mu*mu;
        sh[0] = mu; sh[1] = rsqrtf(var + 1e-5f);
    }
    __syncthreads();
    const float mu = sh[0], rs = sh[1];
    #pragma unroll
    for (int i = 0; i < 16; ++i){
        float4 o;
        o.x = (v[i].x - mu)*rs; o.y = (v[i].y - mu)*rs;
        o.z = (v[i].z - mu)*rs; o.w = (v[i].w - mu)*rs;
        yp[tid + i*256] = o;
    }
}

// ---------------- ksum (scaled by 1/sqrt(C)) ----------------------------------
__global__ __launch_bounds__(256) void ksum_kernel(
    const float* __restrict__ k, float* __restrict__ ks)
{
    const long base = (long)blockIdx.x * NN;
    const float4* kp = (const float4*)(k + base);
    const int tid = threadIdx.x;
    float s = 0.f;
    #pragma unroll
    for (int i = 0; i < 16; ++i){
        float4 t = kp[tid + i*256];
        s += t.x + t.y + t.z + t.w;
    }
    #pragma unroll
    for (int o = 16; o; o >>= 1) s += __shfl_xor_sync(0xffffffffu, s, o);
    __shared__ float sh[8];
    const int w = tid >> 5, lane = tid & 31;
    if (lane == 0) sh[w] = s;
    __syncthreads();
    if (tid == 0){
        float ts = 0.f;
        #pragma unroll
        for (int i = 0; i < 8; ++i) ts += sh[i];
        ks[blockIdx.x] = ts * (1.0f/16.0f);   // / sqrt(C)
    }
}

// ---------------- z = 1/(q . ksum_scaled + N) ----------------------------------
__global__ __launch_bounds__(256) void z_kernel(
    const float* __restrict__ q, const float* __restrict__ ks, float* __restrict__ z)
{
    const int b = blockIdx.y;
    const int n = blockIdx.x * 256 + threadIdx.x;
    __shared__ float s[256];
    s[threadIdx.x] = ks[b*256 + threadIdx.x];
    __syncthreads();
    const float* qb = q + (long)b*BCN + n;
    float a = (float)NN;
    #pragma unroll 8
    for (int c = 0; c < 256; ++c) a += s[c] * qb[(long)c * NN];
    z[(long)b*NN + n] = 1.0f / a;
}

// ---------------- generic 256xN GEMM with epilogue -----------------------------
// Y[b][m][n] = epi( sum_k W[m][k] * X[b][k][n] + bias[m] )
// EPI: 0 gelu, 1 softplus, 2 identity, 3 attn ((acc+v)*z*g)
template<int EPI>
__global__ __launch_bounds__(256) void gemm256_kernel(
    const float* __restrict__ W, const float* __restrict__ bias,
    const float* __restrict__ X, float* __restrict__ Y,
    const float* __restrict__ Vp, const float* __restrict__ Gp,
    const float* __restrict__ Zp, int wBatched)
{
    extern __shared__ float sm[];
    float* WS = sm;              // 2 buffers x 256x36
    float* XS = sm + 2*9216;     // 2 buffers x 32x72
    const int tid = threadIdx.x;
    const int lane = tid & 31, w = tid >> 5;
    const int b = blockIdx.z;
    const long n0 = (long)blockIdx.x * 64;
    const float* Wb = W + (wBatched ? (long)b*CC*CC : 0);
    const float* Xb = X + (long)b*BCN;

    // prologue: chunk 0
    {
        #pragma unroll
        for (int i = 0; i < 8; ++i){
            int idx = tid + i*256, r = idx >> 3, c4 = idx & 7;
            cpa16(WS + r*36 + c4*4, Wb + (long)r*256 + c4*4);
        }
        #pragma unroll
        for (int i = 0; i < 2; ++i){
            int idx = tid + i*256, r = idx >> 4, c4 = idx & 15;
            cpa16(XS + r*72 + c4*4, Xb + (long)r*NN + n0 + c4*4);
        }
        cpacommit();
    }

    float acc[2][8][4];
    #pragma unroll
    for (int mt = 0; mt < 2; ++mt)
        #pragma unroll
        for (int nt = 0; nt < 8; ++nt)
            #pragma unroll
            for (int i = 0; i < 4; ++i) acc[mt][nt][i] = 0.f;

    #pragma unroll 1
    for (int kc = 0; kc < 8; ++kc){
        cpawait();
        __syncthreads();
        if (kc < 7){
            float* ws2 = WS + ((kc+1)&1)*9216;
            float* xs2 = XS + ((kc+1)&1)*2304;
            const int kb = (kc+1)*32;
            #pragma unroll
            for (int i = 0; i < 8; ++i){
                int idx = tid + i*256, r = idx >> 3, c4 = idx & 7;
                cpa16(ws2 + r*36 + c4*4, Wb + (long)r*256 + kb + c4*4);
            }
            #pragma unroll
            for (int i = 0; i < 2; ++i){
                int idx = tid + i*256, r = idx >> 4, c4 = idx & 15;
                cpa16(xs2 + r*72 + c4*4, Xb + (long)(kb+r)*NN + n0 + c4*4);
            }
            cpacommit();
        }
        const float* ws = WS + (kc&1)*9216;
        const float* xs = XS + (kc&1)*2304;
        #pragma unroll
        for (int k8 = 0; k8 < 4; ++k8){
            const int kb = k8*8;
            unsigned a[2][4];
            #pragma unroll
            for (int mt = 0; mt < 2; ++mt){
                const int r = w*32 + mt*16 + (lane>>2);
                const int c = kb + (lane&3);
                a[mt][0] = f2tf(ws[r*36 + c]);
                a[mt][1] = f2tf(ws[(r+8)*36 + c]);
                a[mt][2] = f2tf(ws[r*36 + c + 4]);
                a[mt][3] = f2tf(ws[(r+8)*36 + c + 4]);
            }
            #pragma unroll
            for (int nt = 0; nt < 8; ++nt){
                const int col = nt*8 + (lane>>2);
                const int kr  = kb + (lane&3);
                unsigned b0 = f2tf(xs[kr*72 + col]);
                unsigned b1 = f2tf(xs[(kr+4)*72 + col]);
                mma8(acc[0][nt], a[0], b0, b1);
                mma8(acc[1][nt], a[1], b0, b1);
            }
        }
        __syncthreads();
    }

    // epilogue
    float* Yb = Y + (long)b*BCN;
    #pragma unroll
    for (int mt = 0; mt < 2; ++mt){
        #pragma unroll
        for (int half = 0; half < 2; ++half){
            const int r = w*32 + mt*16 + (lane>>2) + half*8;
            float bi = 0.f;
            if (EPI != 3) bi = bias[r];
            const long rowoff = (long)r*NN + n0;
            #pragma unroll
            for (int nt = 0; nt < 8; ++nt){
                const int c = nt*8 + (lane&3)*2;
                float x0 = acc[mt][nt][half*2+0] + bi;
                float x1 = acc[mt][nt][half*2+1] + bi;
                float2 o;
                if (EPI == 0){ o.x = geluf(x0); o.y = geluf(x1); }
                else if (EPI == 1){ o.x = softplusf(x0); o.y = softplusf(x1); }
                else if (EPI == 2){ o.x = x0; o.y = x1; }
                else {
                    const float2 vv = *(const float2*)(Vp + (long)b*BCN + rowoff + c);
                    const float2 gg = *(const float2*)(Gp + (long)b*BCN + rowoff + c);
                    const float2 zz = *(const float2*)(Zp + (long)b*NN + n0 + c);
                    o.x = (x0 + vv.x) * zz.x * gg.x;
                    o.y = (x1 + vv.y) * zz.y * gg.y;
                }
                *(float2*)(Yb + rowoff + c) = o;
            }
        }
    }
}

// ---------------- kv partial GEMM: P[b][chunk] += k-tile . v-tile^T ------------
__global__ __launch_bounds__(256) void kv_kernel(
    const float* __restrict__ K, const float* __restrict__ V, float* __restrict__ P)
{
    extern __shared__ float sm[];
    float* AS = sm;              // 2 x 128x36
    float* BS = sm + 2*4608;     // 2 x 128x36
    const int tid = threadIdx.x, lane = tid & 31, w = tid >> 5;
    const int wm = w & 3, wn = w >> 2;
    const int c0 = (blockIdx.x & 1) * 128;
    const int d0 = (blockIdx.x >> 1) * 128;
    const int chunk = blockIdx.y;
    const int b = blockIdx.z;
    const float* Kb = K + (long)b*BCN;
    const float* Vb = V + (long)b*BCN;
    const long nbase = (long)chunk * 1024;

    // chunk 0 load
    {
        const long nb = nbase;
        #pragma unroll
        for (int i = 0; i < 4; ++i){
            int idx = tid + i*256, r = idx >> 3, c4 = idx & 7;
            cpa16(AS + r*36 + c4*4, Kb + (long)(c0+r)*NN + nb + c4*4);
            cpa16(BS + r*36 + c4*4, Vb + (long)(d0+r)*NN + nb + c4*4);
        }
        cpacommit();
    }

    float acc[2][8][4];
    #pragma unroll
    for (int mt = 0; mt < 2; ++mt)
        #pragma unroll
        for (int nt = 0; nt < 8; ++nt)
            #pragma unroll
            for (int i = 0; i < 4; ++i) acc[mt][nt][i] = 0.f;

    #pragma unroll 1
    for (int it = 0; it < 32; ++it){
        cpawait();
        __syncthreads();
        if (it < 31){
            float* as2 = AS + ((it+1)&1)*4608;
            float* bs2 = BS + ((it+1)&1)*4608;
            const long nb = nbase + (long)(it+1)*32;
            #pragma unroll
            for (int i = 0; i < 4; ++i){
                int idx = tid + i*256, r = idx >> 3, c4 = idx & 7;
                cpa16(as2 + r*36 + c4*4, Kb + (long)(c0+r)*NN + nb + c4*4);
                cpa16(bs2 + r*36 + c4*4, Vb + (long)(d0+r)*NN + nb + c4*4);
            }
            cpacommit();
        }
        const float* as = AS + (it&1)*4608;
        const float* bs = BS + (it&1)*4608;
        #pragma unroll
        for (int k8 = 0; k8 < 4; ++k8){
            const int kb = k8*8;
            unsigned a[2][4];
            #pragma unroll
            for (int mt = 0; mt < 2; ++mt){
                const int r = wm*32 + mt*16 + (lane>>2);
                const int c = kb + (lane&3);
                a[mt][0] = f2tf(as[r*36 + c]);
                a[mt][1] = f2tf(as[(r+8)*36 + c]);
                a[mt][2] = f2tf(as[r*36 + c + 4]);
                a[mt][3] = f2tf(as[(r+8)*36 + c + 4]);
            }
            #pragma unroll
            for (int nt = 0; nt < 8; ++nt){
                const int d = wn*64 + nt*8 + (lane>>2);
                unsigned b0 = f2tf(bs[d*36 + kb + (lane&3)]);
                unsigned b1 = f2tf(bs[d*36 + kb + 4 + (lane&3)]);
                mma8(acc[0][nt], a[0], b0, b1);
                mma8(acc[1][nt], a[1], b0, b1);
            }
        }
        __syncthreads();
    }

    float* Pb = P + (long)(b*16 + chunk)*CC*CC;
    #pragma unroll
    for (int mt = 0; mt < 2; ++mt){
        #pragma unroll
        for (int half = 0; half < 2; ++half){
            const int r = c0 + wm*32 + mt*16 + (lane>>2) + half*8;
            #pragma unroll
            for (int nt = 0; nt < 8; ++nt){
                const int d = d0 + wn*64 + nt*8 + (lane&3)*2;
                float2 o;
                o.x = acc[mt][nt][half*2+0];
                o.y = acc[mt][nt][half*2+1];
                *(float2*)(Pb + (long)r*CC + d) = o;
            }
        }
    }
}

// ---------------- kv reduce (+transpose, fold 1/sqrt(C)) -----------------------
__global__ __launch_bounds__(256) void kvred_kernel(
    const float* __restrict__ P, float* __restrict__ kvT)
{
    const int o = blockIdx.x * 256 + threadIdx.x;   // 0..262143
    const int b = o >> 16;
    const int c = (o >> 8) & 255;
    const int d = o & 255;
    float s = 0.f;
    #pragma unroll
    for (int ch = 0; ch < 16; ++ch)
        s += P[((long)(b*16 + ch)*256 + c)*256 + d];
    kvT[((long)b*256 + d)*256 + c] = s * (1.0f/16.0f);  // / sqrt(C)
}

// ---------------- host side ----------------------------------------------------
static const size_t GEMM_SMEM = (size_t)(2*9216 + 2*2304) * sizeof(float);  // 92160
static const size_t KV_SMEM   = (size_t)(4*4608) * sizeof(float);           // 73728

static void run_gemm(int epi, const float* W, const float* bias,
                     const float* X, float* Y,
                     const float* Vp, const float* Gp, const float* Zp,
                     int wBatched)
{
    dim3 grid(NN/64, 1, BB);
    switch (epi){
    case 0:
        cudaFuncSetAttribute(gemm256_kernel<0>, cudaFuncAttributeMaxDynamicSharedMemorySize, (int)GEMM_SMEM);
        gemm256_kernel<0><<<grid, 256, GEMM_SMEM>>>(W, bias, X, Y, Vp, Gp, Zp, wBatched);
        break;
    case 1:
        cudaFuncSetAttribute(gemm256_kernel<1>, cudaFuncAttributeMaxDynamicSharedMemorySize, (int)GEMM_SMEM);
        gemm256_kernel<1><<<grid, 256, GEMM_SMEM>>>(W, bias, X, Y, Vp, Gp, Zp, wBatched);
        break;
    case 2:
        cudaFuncSetAttribute(gemm256_kernel<2>, cudaFuncAttributeMaxDynamicSharedMemorySize, (int)GEMM_SMEM);
        gemm256_kernel<2><<<grid, 256, GEMM_SMEM>>>(W, bias, X, Y, Vp, Gp, Zp, wBatched);
        break;
    default:
        cudaFuncSetAttribute(gemm256_kernel<3>, cudaFuncAttributeMaxDynamicSharedMemorySize, (int)GEMM_SMEM);
        gemm256_kernel<3><<<grid, 256, GEMM_SMEM>>>(W, bias, X, Y, Vp, Gp, Zp, wBatched);
        break;
    }
}

extern "C" void kernel_launch(void* const* d_in, const int* in_sizes, int n_in,
                              void* d_out, int out_size)
{
    (void)in_sizes; (void)n_in; (void)out_size;
    const float* x   = (const float*)d_in[0];
    const float* Wq1 = (const float*)d_in[1];  const float* bq1 = (const float*)d_in[2];
    const float* Wq2 = (const float*)d_in[3];  const float* bq2 = (const float*)d_in[4];
    const float* Wk1 = (const float*)d_in[5];  const float* bk1 = (const float*)d_in[6];
    const float* Wk2 = (const float*)d_in[7];  const float* bk2 = (const float*)d_in[8];
    const float* Wv  = (const float*)d_in[9];  const float* bv  = (const float*)d_in[10];
    const float* Wg  = (const float*)d_in[11]; const float* bg  = (const float*)d_in[12];
    const float* Wo  = (const float*)d_in[13]; const float* bo  = (const float*)d_in[14];
    float* out = (float*)d_out;

    float *xn, *t, *q, *k, *v, *g, *kvp, *kvT, *ks, *z;
    cudaGetSymbolAddress((void**)&xn,  g_xn);
    cudaGetSymbolAddress((void**)&t,   g_t);
    cudaGetSymbolAddress((void**)&q,   g_q);
    cudaGetSymbolAddress((void**)&k,   g_k);
    cudaGetSymbolAddress((void**)&v,   g_v);
    cudaGetSymbolAddress((void**)&g,   g_g);
    cudaGetSymbolAddress((void**)&kvp, g_kvp);
    cudaGetSymbolAddress((void**)&kvT, g_kvT);
    cudaGetSymbolAddress((void**)&ks,  g_ks);
    cudaGetSymbolAddress((void**)&z,   g_z);

    // 1. instance norm
    instnorm_kernel<<<BB*CC, 256>>>(x, xn);

    // 2. projections
    run_gemm(0, Wq1, bq1, xn, t, nullptr, nullptr, nullptr, 0);  // gelu
    run_gemm(1, Wq2, bq2, t,  q, nullptr, nullptr, nullptr, 0);  // softplus
    run_gemm(0, Wk1, bk1, xn, t, nullptr, nullptr, nullptr, 0);
    run_gemm(1, Wk2, bk2, t,  k, nullptr, nullptr, nullptr, 0);
    run_gemm(0, Wv,  bv,  xn, v, nullptr, nullptr, nullptr, 0);
    run_gemm(0, Wg,  bg,  xn, g, nullptr, nullptr, nullptr, 0);

    // 3. ksum (scaled), kv partials + reduce(+transpose, 1/sqrt(C))
    ksum_kernel<<<BB*CC, 256>>>(k, ks);
    {
        cudaFuncSetAttribute(kv_kernel, cudaFuncAttributeMaxDynamicSharedMemorySize, (int)KV_SMEM);
        dim3 grid(4, 16, BB);
        kv_kernel<<<grid, 256, KV_SMEM>>>(k, v, kvp);
    }
    kvred_kernel<<<BB*CC, 256>>>(kvp, kvT);

    // 4. z
    {
        dim3 grid(NN/256, BB);
        z_kernel<<<grid, 256>>>(q, ks, z);
    }

    // 5. out_pre = (kvT . q + v) * z * g   (kvT already has 1/sqrt(C))
    run_gemm(3, kvT, nullptr, q, t, v, g, z, 1);

    // 6. final conv1x1
    run_gemm(2, Wo, bo, t, out, nullptr, nullptr, nullptr, 0);
}

// round 2
// speedup vs baseline: 1.0683x; 1.0683x over previous
#include <cuda_runtime.h>
#include <math.h>
#include <stdint.h>

#define CC 256
#define NN 16384
#define BB 4
#define BCN (CC*NN)

// ---------------- scratch (device globals; no allocations allowed) ----------
__device__ float g_xn[BB*BCN];
__device__ float g_t [BB*BCN];   // temp q1-out, later out_pre
__device__ float g_t2[BB*BCN];   // temp k1-out
__device__ float g_q [BB*BCN];
__device__ float g_k [BB*BCN];
__device__ float g_v [BB*BCN];
__device__ float g_g [BB*BCN];
__device__ float g_kvp[BB*16*CC*CC];
__device__ float g_kvT[BB*CC*CC];
__device__ float g_ks [BB*CC];
__device__ float g_z  [BB*NN];

// ---------------- helpers ----------------------------------------------------
__device__ __forceinline__ void cpa16(float* s, const float* g){
    unsigned a = (unsigned)__cvta_generic_to_shared(s);
    asm volatile("cp.async.cg.shared.global [%0], [%1], 16;\n" :: "r"(a), "l"(g));
}
__device__ __forceinline__ void cpacommit(){ asm volatile("cp.async.commit_group;\n"); }
__device__ __forceinline__ void cpawait(){ asm volatile("cp.async.wait_group 0;\n"); }
__device__ __forceinline__ void mma8(float* d, const unsigned* a, unsigned b0, unsigned b1){
    asm volatile(
      "mma.sync.aligned.m16n8k8.row.col.f32.tf32.tf32.f32 "
      "{%0,%1,%2,%3},{%4,%5,%6,%7},{%8,%9},{%0,%1,%2,%3};\n"
      : "+f"(d[0]), "+f"(d[1]), "+f"(d[2]), "+f"(d[3])
      : "r"(a[0]), "r"(a[1]), "r"(a[2]), "r"(a[3]), "r"(b0), "r"(b1));
}
__device__ __forceinline__ unsigned bits(float f){ return __float_as_uint(f); }
__device__ __forceinline__ float geluf(float x){
    return 0.5f * x * (1.0f + erff(x * 0.70710678118654752440f));
}
__device__ __forceinline__ float softplusf(float x){
    return fmaxf(x, 0.0f) + log1pf(expf(-fabsf(x)));
}

// ---------------- instance norm ----------------------------------------------
__global__ __launch_bounds__(256) void instnorm_kernel(
    const float* __restrict__ x, float* __restrict__ y)
{
    const long base = (long)blockIdx.x * NN;
    const float4* xp = (const float4*)(x + base);
    float4* yp = (float4*)(y + base);
    const int tid = threadIdx.x;
    float4 v[16];
    float s = 0.f, s2 = 0.f;
    #pragma unroll
    for (int i = 0; i < 16; ++i){
        v[i] = xp[tid + i*256];
        s  += v[i].x + v[i].y + v[i].z + v[i].w;
        s2 += v[i].x*v[i].x + v[i].y*v[i].y + v[i].z*v[i].z + v[i].w*v[i].w;
    }
    #pragma unroll
    for (int o = 16; o; o >>= 1){
        s  += __shfl_xor_sync(0xffffffffu, s,  o);
        s2 += __shfl_xor_sync(0xffffffffu, s2, o);
    }
    __shared__ float sh[16];
    const int w = tid >> 5, lane = tid & 31;
    if (lane == 0){ sh[w] = s; sh[8+w] = s2; }
    __syncthreads();
    if (tid == 0){
        float ts = 0.f, ts2 = 0.f;
        #pragma unroll
        for (int i = 0; i < 8; ++i){ ts += sh[i]; ts2 += sh[8+i]; }
        float mu  = ts * (1.0f/NN);
        float var = ts2 * (1.0f/NN) - mu*mu;
        sh[0] = mu; sh[1] = rsqrtf(var + 1e-5f);
    }
    __syncthreads();
    const float mu = sh[0], rs = sh[1];
    #pragma unroll
    for (int i = 0; i < 16; ++i){
        float4 o;
        o.x = (v[i].x - mu)*rs; o.y = (v[i].y - mu)*rs;
        o.z = (v[i].z - mu)*rs; o.w = (v[i].w - mu)*rs;
        yp[tid + i*256] = o;
    }
}

// ---------------- ksum (scaled by 1/sqrt(C)) ----------------------------------
__global__ __launch_bounds__(256) void ksum_kernel(
    const float* __restrict__ k, float* __restrict__ ks)
{
    const long base = (long)blockIdx.x * NN;
    const float4* kp = (const float4*)(k + base);
    const int tid = threadIdx.x;
    float s = 0.f;
    #pragma unroll
    for (int i = 0; i < 16; ++i){
        float4 t = kp[tid + i*256];
        s += t.x + t.y + t.z + t.w;
    }
    #pragma unroll
    for (int o = 16; o; o >>= 1) s += __shfl_xor_sync(0xffffffffu, s, o);
    __shared__ float sh[8];
    const int w = tid >> 5, lane = tid & 31;
    if (lane == 0) sh[w] = s;
    __syncthreads();
    if (tid == 0){
        float ts = 0.f;
        #pragma unroll
        for (int i = 0; i < 8; ++i) ts += sh[i];
        ks[blockIdx.x] = ts * (1.0f/16.0f);   // / sqrt(C)
    }
}

// ---------------- z = 1/(q . ksum_scaled + N) ----------------------------------
__global__ __launch_bounds__(256) void z_kernel(
    const float* __restrict__ q, const float* __restrict__ ks, float* __restrict__ z)
{
    const int b = blockIdx.y;
    const int n = blockIdx.x * 256 + threadIdx.x;
    __shared__ float s[256];
    s[threadIdx.x] = ks[b*256 + threadIdx.x];
    __syncthreads();
    const float* qb = q + (long)b*BCN + n;
    float a = (float)NN;
    #pragma unroll 8
    for (int c = 0; c < 256; ++c) a += s[c] * qb[(long)c * NN];
    z[(long)b*NN + n] = 1.0f / a;
}

// ---------------- fused generic 256xN GEMM with epilogue ----------------------
// Up to 4 independent GEMMs per launch (selected by blockIdx.y):
//   Y[y][b][m][n] = epi( sum_k W[y][m][k] * X[y][b][k][n] + bias[y][m] )
// EPI: 0 gelu, 1 softplus, 2 identity, 3 attn ((acc+v)*z*g)
struct Quad {
    const float* W[4];
    const float* B[4];
    const float* X[4];
    float*       Y[4];
};

template<int EPI>
__global__ __launch_bounds__(256) void gemmf_kernel(
    Quad p,
    const float* __restrict__ Vp, const float* __restrict__ Gp,
    const float* __restrict__ Zp, int wBatched)
{
    extern __shared__ float sm[];
    float* WS = sm;              // 2 buffers x 256x36
    float* XS = sm + 2*9216;     // 2 buffers x 32x72
    const int tid = threadIdx.x;
    const int lane = tid & 31, w = tid >> 5;
    const int lq = lane >> 2, lr = lane & 3;
    const int y = blockIdx.y;
    const int b = blockIdx.z;
    const long n0 = (long)blockIdx.x * 64;
    const float* Wb = p.W[y] + (wBatched ? (long)b*CC*CC : 0);
    const float* Xb = p.X[y] + (long)b*BCN;
    float* Yb = p.Y[y] + (long)b*BCN;

    // prologue: chunk 0
    {
        #pragma unroll
        for (int i = 0; i < 8; ++i){
            int idx = tid + i*256, r = idx >> 3, c4 = idx & 7;
            cpa16(WS + r*36 + c4*4, Wb + (long)r*256 + c4*4);
        }
        #pragma unroll
        for (int i = 0; i < 2; ++i){
            int idx = tid + i*256, r = idx >> 4, c4 = idx & 15;
            cpa16(XS + r*72 + c4*4, Xb + (long)r*NN + n0 + c4*4);
        }
        cpacommit();
    }

    float acc[2][8][4];
    #pragma unroll
    for (int mt = 0; mt < 2; ++mt)
        #pragma unroll
        for (int nt = 0; nt < 8; ++nt)
            #pragma unroll
            for (int i = 0; i < 4; ++i) acc[mt][nt][i] = 0.f;

    #pragma unroll 1
    for (int kc = 0; kc < 8; ++kc){
        cpawait();
        __syncthreads();
        if (kc < 7){
            float* ws2 = WS + ((kc+1)&1)*9216;
            float* xs2 = XS + ((kc+1)&1)*2304;
            const int kb = (kc+1)*32;
            #pragma unroll
            for (int i = 0; i < 8; ++i){
                int idx = tid + i*256, r = idx >> 3, c4 = idx & 7;
                cpa16(ws2 + r*36 + c4*4, Wb + (long)r*256 + kb + c4*4);
            }
            #pragma unroll
            for (int i = 0; i < 2; ++i){
                int idx = tid + i*256, r = idx >> 4, c4 = idx & 15;
                cpa16(xs2 + r*72 + c4*4, Xb + (long)(kb+r)*NN + n0 + c4*4);
            }
            cpacommit();
        }
        const float* wsA = WS + (kc&1)*9216 + (w*32 + lq)*36 + lr;
        const float* xsB = XS + (kc&1)*2304 + lr*72 + lq;
        #pragma unroll
        for (int k8 = 0; k8 < 4; ++k8){
            const int kb = k8*8;
            unsigned a[2][4];
            #pragma unroll
            for (int mt = 0; mt < 2; ++mt){
                a[mt][0] = bits(wsA[(mt*16  )*36 + kb    ]);
                a[mt][1] = bits(wsA[(mt*16+8)*36 + kb    ]);
                a[mt][2] = bits(wsA[(mt*16  )*36 + kb + 4]);
                a[mt][3] = bits(wsA[(mt*16+8)*36 + kb + 4]);
            }
            #pragma unroll
            for (int nt = 0; nt < 8; ++nt){
                unsigned b0 = bits(xsB[ kb   *72 + nt*8]);
                unsigned b1 = bits(xsB[(kb+4)*72 + nt*8]);
                mma8(acc[0][nt], a[0], b0, b1);
                mma8(acc[1][nt], a[1], b0, b1);
            }
        }
        __syncthreads();
    }

    // epilogue
    #pragma unroll
    for (int mt = 0; mt < 2; ++mt){
        #pragma unroll
        for (int half = 0; half < 2; ++half){
            const int r = w*32 + mt*16 + lq + half*8;
            float bi = 0.f;
            if (EPI != 3) bi = p.B[y][r];
            const long rowoff = (long)r*NN + n0;
            #pragma unroll
            for (int nt = 0; nt < 8; ++nt){
                const int c = nt*8 + lr*2;
                float x0 = acc[mt][nt][half*2+0] + bi;
                float x1 = acc[mt][nt][half*2+1] + bi;
                float2 o;
                if (EPI == 0){ o.x = geluf(x0); o.y = geluf(x1); }
                else if (EPI == 1){ o.x = softplusf(x0); o.y = softplusf(x1); }
                else if (EPI == 2){ o.x = x0; o.y = x1; }
                else {
                    const float2 vv = *(const float2*)(Vp + (long)b*BCN + rowoff + c);
                    const float2 gg = *(const float2*)(Gp + (long)b*BCN + rowoff + c);
                    const float2 zz = *(const float2*)(Zp + (long)b*NN + n0 + c);
                    o.x = (x0 + vv.x) * zz.x * gg.x;
                    o.y = (x1 + vv.y) * zz.y * gg.y;
                }
                *(float2*)(Yb + rowoff + c) = o;
            }
        }
    }
}

// ---------------- kv partial GEMM: P[b][chunk] = k-tile . v-tile^T -------------
__global__ __launch_bounds__(256) void kv_kernel(
    const float* __restrict__ K, const float* __restrict__ V, float* __restrict__ P)
{
    extern __shared__ float sm[];
    float* AS = sm;              // 2 x 128x36
    float* BS = sm + 2*4608;     // 2 x 128x36
    const int tid = threadIdx.x, lane = tid & 31, w = tid >> 5;
    const int lq = lane >> 2, lr = lane & 3;
    const int wm = w & 3, wn = w >> 2;
    const int c0 = (blockIdx.x & 1) * 128;
    const int d0 = (blockIdx.x >> 1) * 128;
    const int chunk = blockIdx.y;
    const int b = blockIdx.z;
    const float* Kb = K + (long)b*BCN;
    const float* Vb = V + (long)b*BCN;
    const long nbase = (long)chunk * 1024;

    {
        const long nb = nbase;
        #pragma unroll
        for (int i = 0; i < 4; ++i){
            int idx = tid + i*256, r = idx >> 3, c4 = idx & 7;
            cpa16(AS + r*36 + c4*4, Kb + (long)(c0+r)*NN + nb + c4*4);
            cpa16(BS + r*36 + c4*4, Vb + (long)(d0+r)*NN + nb + c4*4);
        }
        cpacommit();
    }

    float acc[2][8][4];
    #pragma unroll
    for (int mt = 0; mt < 2; ++mt)
        #pragma unroll
        for (int nt = 0; nt < 8; ++nt)
            #pragma unroll
            for (int i = 0; i < 4; ++i) acc[mt][nt][i] = 0.f;

    #pragma unroll 1
    for (int it = 0; it < 32; ++it){
        cpawait();
        __syncthreads();
        if (it < 31){
            float* as2 = AS + ((it+1)&1)*4608;
            float* bs2 = BS + ((it+1)&1)*4608;
            const long nb = nbase + (long)(it+1)*32;
            #pragma unroll
            for (int i = 0; i < 4; ++i){
                int idx = tid + i*256, r = idx >> 3, c4 = idx & 7;
                cpa16(as2 + r*36 + c4*4, Kb + (long)(c0+r)*NN + nb + c4*4);
                cpa16(bs2 + r*36 + c4*4, Vb + (long)(d0+r)*NN + nb + c4*4);
            }
            cpacommit();
        }
        const float* asA = AS + (it&1)*4608 + (wm*32 + lq)*36 + lr;
        const float* bsB = BS + (it&1)*4608 + (wn*64 + lq)*36 + lr;
        #pragma unroll
        for (int k8 = 0; k8 < 4; ++k8){
            const int kb = k8*8;
            unsigned a[2][4];
            #pragma unroll
            for (int mt = 0; mt < 2; ++mt){
                a[mt][0] = bits(asA[(mt*16  )*36 + kb    ]);
                a[mt][1] = bits(asA[(mt*16+8)*36 + kb    ]);
                a[mt][2] = bits(asA[(mt*16  )*36 + kb + 4]);
                a[mt][3] = bits(asA[(mt*16+8)*36 + kb + 4]);
            }
            #pragma unroll
            for (int nt = 0; nt < 8; ++nt){
                unsigned b0 = bits(bsB[nt*8*36 + kb    ]);
                unsigned b1 = bits(bsB[nt*8*36 + kb + 4]);
                mma8(acc[0][nt], a[0], b0, b1);
                mma8(acc[1][nt], a[1], b0, b1);
            }
        }
        __syncthreads();
    }

    float* Pb = P + (long)(b*16 + chunk)*CC*CC;
    #pragma unroll
    for (int mt = 0; mt < 2; ++mt){
        #pragma unroll
        for (int half = 0; half < 2; ++half){
            const int r = c0 + wm*32 + mt*16 + lq + half*8;
            #pragma unroll
            for (int nt = 0; nt < 8; ++nt){
                const int d = d0 + wn*64 + nt*8 + lr*2;
                float2 o;
                o.x = acc[mt][nt][half*2+0];
                o.y = acc[mt][nt][half*2+1];
                *(float2*)(Pb + (long)r*CC + d) = o;
            }
        }
    }
}

// ---------------- kv reduce (+transpose, fold 1/sqrt(C)) -----------------------
__global__ __launch_bounds__(256) void kvred_kernel(
    const float* __restrict__ P, float* __restrict__ kvT)
{
    const int o = blockIdx.x * 256 + threadIdx.x;   // 0..262143
    const int b = o >> 16;
    const int c = (o >> 8) & 255;
    const int d = o & 255;
    float s = 0.f;
    #pragma unroll
    for (int ch = 0; ch < 16; ++ch)
        s += P[((long)(b*16 + ch)*256 + c)*256 + d];
    kvT[((long)b*256 + d)*256 + c] = s * (1.0f/16.0f);  // / sqrt(C)
}

// ---------------- host side ----------------------------------------------------
static const size_t GEMM_SMEM = (size_t)(2*9216 + 2*2304) * sizeof(float);  // 92160
static const size_t KV_SMEM   = (size_t)(4*4608) * sizeof(float);           // 73728

template<int EPI>
static void run_gemmf(const Quad& p, int nfused,
                      const float* Vp, const float* Gp, const float* Zp,
                      int wBatched)
{
    static bool attrSet[4] = {false,false,false,false};
    if (!attrSet[EPI]){
        cudaFuncSetAttribute(gemmf_kernel<EPI>, cudaFuncAttributeMaxDynamicSharedMemorySize, (int)GEMM_SMEM);
        attrSet[EPI] = true;
    }
    dim3 grid(NN/64, nfused, BB);
    gemmf_kernel<EPI><<<grid, 256, GEMM_SMEM>>>(p, Vp, Gp, Zp, wBatched);
}

extern "C" void kernel_launch(void* const* d_in, const int* in_sizes, int n_in,
                              void* d_out, int out_size)
{
    (void)in_sizes; (void)n_in; (void)out_size;
    const float* x   = (const float*)d_in[0];
    const float* Wq1 = (const float*)d_in[1];  const float* bq1 = (const float*)d_in[2];
    const float* Wq2 = (const float*)d_in[3];  const float* bq2 = (const float*)d_in[4];
    const float* Wk1 = (const float*)d_in[5];  const float* bk1 = (const float*)d_in[6];
    const float* Wk2 = (const float*)d_in[7];  const float* bk2 = (const float*)d_in[8];
    const float* Wv  = (const float*)d_in[9];  const float* bv  = (const float*)d_in[10];
    const float* Wg  = (const float*)d_in[11]; const float* bg  = (const float*)d_in[12];
    const float* Wo  = (const float*)d_in[13]; const float* bo  = (const float*)d_in[14];
    float* out = (float*)d_out;

    float *xn, *t, *t2, *q, *k, *v, *g, *kvp, *kvT, *ks, *z;
    cudaGetSymbolAddress((void**)&xn,  g_xn);
    cudaGetSymbolAddress((void**)&t,   g_t);
    cudaGetSymbolAddress((void**)&t2,  g_t2);
    cudaGetSymbolAddress((void**)&q,   g_q);
    cudaGetSymbolAddress((void**)&k,   g_k);
    cudaGetSymbolAddress((void**)&v,   g_v);
    cudaGetSymbolAddress((void**)&g,   g_g);
    cudaGetSymbolAddress((void**)&kvp, g_kvp);
    cudaGetSymbolAddress((void**)&kvT, g_kvT);
    cudaGetSymbolAddress((void**)&ks,  g_ks);
    cudaGetSymbolAddress((void**)&z,   g_z);

    // 1. instance norm
    instnorm_kernel<<<BB*CC, 256>>>(x, xn);

    // 2. stage-1 projections (all gelu): q1, k1, v, g  — one fused launch
    {
        Quad p;
        p.W[0]=Wq1; p.B[0]=bq1; p.X[0]=xn; p.Y[0]=t;
        p.W[1]=Wk1; p.B[1]=bk1; p.X[1]=xn; p.Y[1]=t2;
        p.W[2]=Wv;  p.B[2]=bv;  p.X[2]=xn; p.Y[2]=v;
        p.W[3]=Wg;  p.B[3]=bg;  p.X[3]=xn; p.Y[3]=g;
        run_gemmf<0>(p, 4, nullptr, nullptr, nullptr, 0);
    }

    // 3. stage-2 projections (softplus): q2, k2 — one fused launch
    {
        Quad p;
        p.W[0]=Wq2; p.B[0]=bq2; p.X[0]=t;  p.Y[0]=q;
        p.W[1]=Wk2; p.B[1]=bk2; p.X[1]=t2; p.Y[1]=k;
        p.W[2]=Wq2; p.B[2]=bq2; p.X[2]=t;  p.Y[2]=q;   // unused
        p.W[3]=Wq2; p.B[3]=bq2; p.X[3]=t;  p.Y[3]=q;   // unused
        run_gemmf<1>(p, 2, nullptr, nullptr, nullptr, 0);
    }

    // 4. ksum (scaled), kv partials + reduce(+transpose, 1/sqrt(C))
    ksum_kernel<<<BB*CC, 256>>>(k, ks);
    {
        cudaFuncSetAttribute(kv_kernel, cudaFuncAttributeMaxDynamicSharedMemorySize, (int)KV_SMEM);
        dim3 grid(4, 16, BB);
        kv_kernel<<<grid, 256, KV_SMEM>>>(k, v, kvp);
    }
    kvred_kernel<<<BB*CC, 256>>>(kvp, kvT);

    // 5. z
    {
        dim3 grid(NN/256, BB);
        z_kernel<<<grid, 256>>>(q, ks, z);
    }

    // 6. out_pre = (kvT . q + v) * z * g   (kvT already has 1/sqrt(C))
    {
        Quad p;
        p.W[0]=kvT; p.B[0]=nullptr; p.X[0]=q; p.Y[0]=t;
        p.W[1]=kvT; p.B[1]=nullptr; p.X[1]=q; p.Y[1]=t;
        p.W[2]=kvT; p.B[2]=nullptr; p.X[2]=q; p.Y[2]=t;
        p.W[3]=kvT; p.B[3]=nullptr; p.X[3]=q; p.Y[3]=t;
        run_gemmf<3>(p, 1, v, g, z, 1);
    }

    // 7. final conv1x1
    {
        Quad p;
        p.W[0]=Wo; p.B[0]=bo; p.X[0]=t; p.Y[0]=out;
        p.W[1]=Wo; p.B[1]=bo; p.X[1]=t; p.Y[1]=out;
        p.W[2]=Wo; p.B[2]=bo; p.X[2]=t; p.Y[2]=out;
        p.W[3]=Wo; p.B[3]=bo; p.X[3]=t; p.Y[3]=out;
        run_gemmf<2>(p, 1, t, t, t, 0);
    }
}